// round 3
// baseline (speedup 1.0000x reference)
#include <cuda_runtime.h>

#define Bq 16
#define Tq 2048
#define Dq 256
#define Nq 512

#define Q_ELEMS (Bq*Tq*Dq)          /* 8388608 */
#define DIFF_OFF Q_ELEMS
#define IND_OFF  (Q_ELEMS + 1)

// ---------------- scratch (no allocations allowed) ----------------
__device__ float g_cb[Bq*Nq*Dq];              // e codebook [b][n][d], 8 MB
__device__ float g_see[Bq*Nq];                // sum(e^2), XLA-tree order
__device__ float g_sxx[Bq*Tq];                // sum(x^2), XLA-tree order
__device__ unsigned long long g_best[Bq*Tq];  // packed (score,~n) argmax keys
__device__ double g_diff_partial[4096];

// ---------------- helpers ----------------
__device__ __forceinline__ unsigned long long make_key(float s, int n) {
    unsigned u = __float_as_uint(s);
    u = (u & 0x80000000u) ? ~u : (u | 0x80000000u);   // order-preserving float->uint
    return ((unsigned long long)u << 32) | (unsigned long long)(0xFFFFFFFFu - (unsigned)n);
}

__device__ __forceinline__ unsigned long long fma2(unsigned long long a,
                                                   unsigned long long x,
                                                   unsigned long long e) {
    asm("fma.rn.f32x2 %0, %1, %2, %0;" : "+l"(a) : "l"(x), "l"(e));
    return a;
}

// XLA warp-tree: shfl_down with descending offsets, acc = rn(acc + other)
__device__ __forceinline__ float warp_tree_sum(float p) {
#pragma unroll
    for (int off = 16; off > 0; off >>= 1)
        p = __fadd_rn(p, __shfl_down_sync(0xffffffffu, p, off));
    return p;
}

// ---------------- kernel 0: reset argmax keys ----------------
__global__ void k_init() {
    int i = blockIdx.x * blockDim.x + threadIdx.x;
    if (i < Bq*Tq) g_best[i] = 0ull;
}

// ---------------- kernel 0b: sxx[t], XLA row-reduce order ----------------
// lane l: partial over x[l+32j]^2, j ascending; then shuffle tree.
__global__ __launch_bounds__(256) void k_prep(const float* __restrict__ x) {
    int tid = threadIdx.x, lane = tid & 31, wid = tid >> 5;
    int token = blockIdx.x * 8 + wid;
    const float* xt = x + (size_t)token * Dq;
    float p = 0.f;
#pragma unroll
    for (int j = 0; j < 8; j++) {
        float c = xt[lane + 32*j];
        p = __fadd_rn(p, __fmul_rn(c, c));
    }
    p = warp_tree_sum(p);
    if (lane == 0) g_sxx[token] = p;
}

// ---------------- kernel 1: codebook build ----------------
// cb: sequential-k fp32 FMA (cublas order). norm/see: XLA tree order.
__global__ __launch_bounds__(128) void k_codebook(const float* __restrict__ emb,
                                                  const float* __restrict__ spk) {
    __shared__ float As[256*33];   // k-chunk staging; reused as [16][258] in epilogue
    __shared__ float Ms[16*32];
    __shared__ float normS[16];

    int tid = threadIdx.x;
    int lane = tid & 31, wid = tid >> 5;
    int n = blockIdx.x;
    const float* embn = emb + (size_t)n * (Dq*Dq);
    const float* mul  = spk + 2*Bq*Dq;   // spk[2] : [b][k]
    const float* addv = spk + 1*Bq*Dq;   // spk[1] : [b][d]

    float acc[2][16];
#pragma unroll
    for (int r = 0; r < 2; r++)
#pragma unroll
        for (int b = 0; b < 16; b++) acc[r][b] = 0.f;

    for (int kc = 0; kc < 256; kc += 32) {
        __syncthreads();
        for (int i = tid; i < 16*32; i += 128) {
            int b = i >> 5, j = i & 31;
            Ms[i] = mul[b*256 + kc + j];
        }
        for (int f = tid; f < 2048; f += 128) {
            int d = f >> 3, jg = f & 7;
            float4 v = *(const float4*)(embn + (size_t)d*256 + kc + jg*4);
            int base = d*33 + jg*4;
            As[base+0] = v.x; As[base+1] = v.y; As[base+2] = v.z; As[base+3] = v.w;
        }
        __syncthreads();

        const float* a0 = As + tid*33;
        const float* a1 = As + (tid+128)*33;
#pragma unroll 4
        for (int j = 0; j < 32; j++) {
            float x0 = a0[j], x1 = a1[j];
#pragma unroll
            for (int b = 0; b < 16; b++) {
                float m = Ms[b*32 + j];
                acc[0][b] = __fmaf_rn(x0, m, acc[0][b]);
                acc[1][b] = __fmaf_rn(x1, m, acc[1][b]);
            }
        }
    }

    // stage cb to smem as [b][258]
    __syncthreads();
#pragma unroll
    for (int r = 0; r < 2; r++)
#pragma unroll
        for (int b = 0; b < 16; b++) As[b*258 + tid + r*128] = acc[r][b];
    __syncthreads();

    // norm[b] = sqrt( tree-sum cb^2 ): warp w handles b = 4w..4w+3
#pragma unroll
    for (int bb = 0; bb < 4; bb++) {
        int b = wid*4 + bb;
        const float* row = As + b*258;
        float p = 0.f;
#pragma unroll
        for (int j = 0; j < 8; j++) {
            float c = row[lane + 32*j];
            p = __fadd_rn(p, __fmul_rn(c, c));
        }
        p = warp_tree_sum(p);
        if (lane == 0) normS[b] = __fsqrt_rn(p);
    }
    __syncthreads();

    // e = cb/norm + add  (true fp32 div, rn add); store + restage
#pragma unroll
    for (int r = 0; r < 2; r++) {
        int d = tid + r*128;
#pragma unroll
        for (int b = 0; b < 16; b++) {
            float ef = __fadd_rn(__fdiv_rn(acc[r][b], normS[b]), addv[b*256 + d]);
            g_cb[((size_t)(b*Nq + n))*Dq + d] = ef;
            As[b*258 + d] = ef;
        }
    }
    __syncthreads();

    // see[b,n] = tree-sum e^2
#pragma unroll
    for (int bb = 0; bb < 4; bb++) {
        int b = wid*4 + bb;
        const float* row = As + b*258;
        float p = 0.f;
#pragma unroll
        for (int j = 0; j < 8; j++) {
            float c = row[lane + 32*j];
            p = __fadd_rn(p, __fmul_rn(c, c));
        }
        p = warp_tree_sum(p);
        if (lane == 0) g_see[b*Nq + n] = p;
    }
}

// ---------------- kernel 2: fused score GEMM + argmax ----------------
// dist[t,n] = (sxx[t] - 2*dot) + see[n]; argmax(-dist), ties -> smallest n
#define KC 16
__global__ __launch_bounds__(256, 2) void k_scores(const float* __restrict__ x) {
    __shared__ float Xs[KC*264];   // [k][256] : x duplicated in pairs, pad 264
    __shared__ float Es[KC*132];   // [k][128], pad 132

    int tid = threadIdx.x;
    int tx = tid & 15, ty = tid >> 4;
    int t0 = blockIdx.x * 128;
    int n0 = blockIdx.y * 128;
    int b  = blockIdx.z;

    const float* xb = x    + ((size_t)b*Tq + t0) * Dq;
    const float* eb = g_cb + ((size_t)b*Nq + n0) * Dq;

    unsigned long long acc[8][4];
#pragma unroll
    for (int i = 0; i < 8; i++)
#pragma unroll
        for (int j = 0; j < 4; j++) acc[i][j] = 0ull;

    for (int kc = 0; kc < 256; kc += KC) {
        __syncthreads();
#pragma unroll
        for (int p = 0; p < 2; p++) {
            int f = tid + p*256;
            int r = f >> 2, jg = f & 3;
            float4 v = *(const float4*)(xb + (size_t)r*Dq + kc + jg*4);
            int kb = jg*4;
            Xs[(kb+0)*264 + r*2] = v.x; Xs[(kb+0)*264 + r*2+1] = v.x;
            Xs[(kb+1)*264 + r*2] = v.y; Xs[(kb+1)*264 + r*2+1] = v.y;
            Xs[(kb+2)*264 + r*2] = v.z; Xs[(kb+2)*264 + r*2+1] = v.z;
            Xs[(kb+3)*264 + r*2] = v.w; Xs[(kb+3)*264 + r*2+1] = v.w;
        }
#pragma unroll
        for (int p = 0; p < 2; p++) {
            int f = tid + p*256;
            int r = f >> 2, jg = f & 3;
            float4 v = *(const float4*)(eb + (size_t)r*Dq + kc + jg*4);
            int kb = jg*4;
            Es[(kb+0)*132 + r] = v.x;
            Es[(kb+1)*132 + r] = v.y;
            Es[(kb+2)*132 + r] = v.z;
            Es[(kb+3)*132 + r] = v.w;
        }
        __syncthreads();

#pragma unroll
        for (int k = 0; k < KC; k++) {
            const unsigned long long* xp = (const unsigned long long*)(Xs + k*264 + ty*16);
            const unsigned long long* ep = (const unsigned long long*)(Es + k*132 + tx*8);
            unsigned long long xv[8], ev[4];
#pragma unroll
            for (int i = 0; i < 8; i++) xv[i] = xp[i];
#pragma unroll
            for (int j = 0; j < 4; j++) ev[j] = ep[j];
#pragma unroll
            for (int i = 0; i < 8; i++)
#pragma unroll
                for (int j = 0; j < 4; j++)
                    acc[i][j] = fma2(acc[i][j], xv[i], ev[j]);
        }
    }

    // epilogue: dist = (sxx - 2*dot) + see, exactly as reference
    float see8[8];
#pragma unroll
    for (int j = 0; j < 8; j++) see8[j] = g_see[b*Nq + n0 + tx*8 + j];

    int trow = t0 + ty*8;
#pragma unroll
    for (int i = 0; i < 8; i++) {
        float sxx = g_sxx[b*Tq + trow + i];
        unsigned long long best = 0ull;
#pragma unroll
        for (int j2 = 0; j2 < 4; j2++) {
            unsigned long long a = acc[i][j2];
            float dlo = __uint_as_float((unsigned)a);
            float dhi = __uint_as_float((unsigned)(a >> 32));
            float distlo = __fadd_rn(__fsub_rn(sxx, __fmul_rn(2.0f, dlo)), see8[j2*2]);
            float disthi = __fadd_rn(__fsub_rn(sxx, __fmul_rn(2.0f, dhi)), see8[j2*2+1]);
            int nlo = n0 + tx*8 + j2*2;
            unsigned long long klo = make_key(-distlo, nlo);
            unsigned long long khi = make_key(-disthi, nlo + 1);
            if (klo > best) best = klo;
            if (khi > best) best = khi;
        }
#pragma unroll
        for (int off = 8; off > 0; off >>= 1) {
            unsigned long long o = __shfl_down_sync(0xffffffffu, best, off, 16);
            if (o > best) best = o;
        }
        if (tx == 0) atomicMax(&g_best[b*Tq + trow + i], best);
    }
}

// ---------------- kernel 3: gather + outputs + diff partials ----------------
__global__ __launch_bounds__(256) void k_gather(const float* __restrict__ x,
                                                float* __restrict__ out) {
    __shared__ double s_red[8];
    int tid = threadIdx.x, lane = tid & 31, wid = tid >> 5;
    int token = blockIdx.x * 8 + wid;
    int b = token >> 11;

    unsigned long long key = g_best[token];
    unsigned n = 0xFFFFFFFFu - (unsigned)key;

    const float4* q4 = (const float4*)(g_cb + ((size_t)(b*Nq) + n) * Dq);
    const float4* x4 = (const float4*)(x + (size_t)token * Dq);
    float4* o4 = (float4*)(out + (size_t)token * Dq);

    double s = 0.0;
#pragma unroll
    for (int p = 0; p < 2; p++) {
        int f = lane + p*32;
        float4 q = q4[f], xv = x4[f];
        float4 r;
        // exactly: (q + (x + (q - x))) * 0.5  (matches ref fp32 op order)
        float dx = __fsub_rn(q.x, xv.x), dy = __fsub_rn(q.y, xv.y);
        float dz = __fsub_rn(q.z, xv.z), dw = __fsub_rn(q.w, xv.w);
        r.x = __fmul_rn(__fadd_rn(q.x, __fadd_rn(xv.x, dx)), 0.5f);
        r.y = __fmul_rn(__fadd_rn(q.y, __fadd_rn(xv.y, dy)), 0.5f);
        r.z = __fmul_rn(__fadd_rn(q.z, __fadd_rn(xv.z, dz)), 0.5f);
        r.w = __fmul_rn(__fadd_rn(q.w, __fadd_rn(xv.w, dw)), 0.5f);
        o4[f] = r;
        s += (double)dx*(double)dx + (double)dy*(double)dy
           + (double)dz*(double)dz + (double)dw*(double)dw;
    }
    if (lane == 0) out[IND_OFF + token] = (float)n;

#pragma unroll
    for (int off = 16; off > 0; off >>= 1) s += __shfl_down_sync(0xffffffffu, s, off);
    if (lane == 0) s_red[wid] = s;
    __syncthreads();
    if (tid == 0) {
        double t = 0.0;
        for (int i = 0; i < 8; i++) t += s_red[i];
        g_diff_partial[blockIdx.x] = t;
    }
}

// ---------------- kernel 4: deterministic final diff reduce ----------------
__global__ __launch_bounds__(256) void k_diff(float* __restrict__ out) {
    __shared__ double sr[256];
    int tid = threadIdx.x;
    double s = 0.0;
    for (int i = tid; i < 4096; i += 256) s += g_diff_partial[i];
    sr[tid] = s;
    __syncthreads();
    for (int off = 128; off > 0; off >>= 1) {
        if (tid < off) sr[tid] += sr[tid + off];
        __syncthreads();
    }
    if (tid == 0) out[DIFF_OFF] = (float)(sr[0] / (double)Q_ELEMS);
}

// ---------------- launch ----------------
extern "C" void kernel_launch(void* const* d_in, const int* in_sizes, int n_in,
                              void* d_out, int out_size) {
    const float* inp = (const float*)d_in[0];   // (16,2048,256)
    const float* spk = (const float*)d_in[1];   // (3,16,256)
    const float* emb = (const float*)d_in[2];   // (512,256,256)
    float* out = (float*)d_out;                 // [quantize | diff | embed_ind]

    k_init<<<32, 1024>>>();
    k_prep<<<Bq*Tq/8, 256>>>(inp);
    k_codebook<<<512, 128>>>(emb, spk);
    dim3 g3(Tq/128, Nq/128, Bq);
    k_scores<<<g3, 256>>>(inp);
    k_gather<<<Bq*Tq/8, 256>>>(inp, out);
    k_diff<<<1, 256>>>(out);
}

// round 4
// speedup vs baseline: 1.0167x; 1.0167x over previous
#include <cuda_runtime.h>

#define Bq 16
#define Tq 2048
#define Dq 256
#define Nq 512

#define Q_ELEMS (Bq*Tq*Dq)          /* 8388608 */
#define DIFF_OFF Q_ELEMS
#define IND_OFF  (Q_ELEMS + 1)

// ---------------- scratch (no allocations allowed) ----------------
__device__ float g_cb[Bq*Nq*Dq];              // e codebook [b][n][d], 8 MB
__device__ float g_see[Bq*Nq];                // sum(e^2), XLA-tree order
__device__ float g_sxx[Bq*Tq];                // sum(x^2), XLA-tree order
__device__ unsigned long long g_best[Bq*Tq];  // packed (score,~n) argmax keys
__device__ double g_diff_partial[4096];

// ---------------- helpers ----------------
__device__ __forceinline__ unsigned long long make_key(float s, int n) {
    unsigned u = __float_as_uint(s);
    u = (u & 0x80000000u) ? ~u : (u | 0x80000000u);   // order-preserving float->uint
    return ((unsigned long long)u << 32) | (unsigned long long)(0xFFFFFFFFu - (unsigned)n);
}

__device__ __forceinline__ unsigned long long fma2(unsigned long long a,
                                                   unsigned long long x,
                                                   unsigned long long e) {
    asm("fma.rn.f32x2 %0, %1, %2, %0;" : "+l"(a) : "l"(x), "l"(e));
    return a;
}

// XLA warp-tree: shfl_down with descending offsets, acc = rn(acc + other)
__device__ __forceinline__ float warp_tree_sum(float p) {
#pragma unroll
    for (int off = 16; off > 0; off >>= 1)
        p = __fadd_rn(p, __shfl_down_sync(0xffffffffu, p, off));
    return p;
}

// ---------------- kernel 0: sxx[t] (XLA order) + g_best reset ----------------
__global__ __launch_bounds__(256) void k_prep(const float* __restrict__ x) {
    int tid = threadIdx.x, lane = tid & 31, wid = tid >> 5;
    int token = blockIdx.x * 8 + wid;
    const float* xt = x + (size_t)token * Dq;
    float p = 0.f;
#pragma unroll
    for (int j = 0; j < 8; j++) {
        float c = xt[lane + 32*j];
        p = __fadd_rn(p, __fmul_rn(c, c));
    }
    p = warp_tree_sum(p);
    if (lane == 0) {
        g_sxx[token] = p;
        g_best[token] = 0ull;
    }
}

// ---------------- kernel 1: codebook build ----------------
// cb: sequential-k fp32 FMA (cublas order). norm/see: XLA tree order.
__global__ __launch_bounds__(128) void k_codebook(const float* __restrict__ emb,
                                                  const float* __restrict__ spk) {
    __shared__ float As[256*33];   // k-chunk staging; reused as [16][258] in epilogue
    __shared__ float Ms[16*32];
    __shared__ float normS[16];

    int tid = threadIdx.x;
    int lane = tid & 31, wid = tid >> 5;
    int n = blockIdx.x;
    const float* embn = emb + (size_t)n * (Dq*Dq);
    const float* mul  = spk + 2*Bq*Dq;   // spk[2] : [b][k]
    const float* addv = spk + 1*Bq*Dq;   // spk[1] : [b][d]

    float acc[2][16];
#pragma unroll
    for (int r = 0; r < 2; r++)
#pragma unroll
        for (int b = 0; b < 16; b++) acc[r][b] = 0.f;

    for (int kc = 0; kc < 256; kc += 32) {
        __syncthreads();
        for (int i = tid; i < 16*32; i += 128) {
            int b = i >> 5, j = i & 31;
            Ms[i] = mul[b*256 + kc + j];
        }
        for (int f = tid; f < 2048; f += 128) {
            int d = f >> 3, jg = f & 7;
            float4 v = *(const float4*)(embn + (size_t)d*256 + kc + jg*4);
            int base = d*33 + jg*4;
            As[base+0] = v.x; As[base+1] = v.y; As[base+2] = v.z; As[base+3] = v.w;
        }
        __syncthreads();

        const float* a0 = As + tid*33;
        const float* a1 = As + (tid+128)*33;
#pragma unroll 4
        for (int j = 0; j < 32; j++) {
            float x0 = a0[j], x1 = a1[j];
#pragma unroll
            for (int b = 0; b < 16; b++) {
                float m = Ms[b*32 + j];
                acc[0][b] = __fmaf_rn(x0, m, acc[0][b]);
                acc[1][b] = __fmaf_rn(x1, m, acc[1][b]);
            }
        }
    }

    // stage cb to smem as [b][258]
    __syncthreads();
#pragma unroll
    for (int r = 0; r < 2; r++)
#pragma unroll
        for (int b = 0; b < 16; b++) As[b*258 + tid + r*128] = acc[r][b];
    __syncthreads();

    // norm[b] = sqrt( tree-sum cb^2 ): warp w handles b = 4w..4w+3
#pragma unroll
    for (int bb = 0; bb < 4; bb++) {
        int b = wid*4 + bb;
        const float* row = As + b*258;
        float p = 0.f;
#pragma unroll
        for (int j = 0; j < 8; j++) {
            float c = row[lane + 32*j];
            p = __fadd_rn(p, __fmul_rn(c, c));
        }
        p = warp_tree_sum(p);
        if (lane == 0) normS[b] = __fsqrt_rn(p);
    }
    __syncthreads();

    // e = cb/norm + add  (true fp32 div, rn add); store + restage
#pragma unroll
    for (int r = 0; r < 2; r++) {
        int d = tid + r*128;
#pragma unroll
        for (int b = 0; b < 16; b++) {
            float ef = __fadd_rn(__fdiv_rn(acc[r][b], normS[b]), addv[b*256 + d]);
            g_cb[((size_t)(b*Nq + n))*Dq + d] = ef;
            As[b*258 + d] = ef;
        }
    }
    __syncthreads();

    // see[b,n] = tree-sum e^2
#pragma unroll
    for (int bb = 0; bb < 4; bb++) {
        int b = wid*4 + bb;
        const float* row = As + b*258;
        float p = 0.f;
#pragma unroll
        for (int j = 0; j < 8; j++) {
            float c = row[lane + 32*j];
            p = __fadd_rn(p, __fmul_rn(c, c));
        }
        p = warp_tree_sum(p);
        if (lane == 0) g_see[b*Nq + n] = p;
    }
}

// ---------------- kernel 2: fused score GEMM + argmax (pipelined) ----------
// dist[t,n] = (sxx[t] - 2*dot) + see[n]; argmax(-dist), ties -> smallest n
// 128t x 128n tile, 2-stage smem ping-pong, reg-prefetch, 1 sync per chunk.
#define KC 16
__global__ __launch_bounds__(256, 2) void k_scores(const float* __restrict__ x) {
    __shared__ float Xs[2][KC*256];   // [k][256] : x duplicated in pairs
    __shared__ float Es[2][KC*128];   // [k][128]
    // 2*16*256*4 + 2*16*128*4 = 32768 + 16384 = 49152 B (static limit exact)

    int tid = threadIdx.x;
    int tx = tid & 15, ty = tid >> 4;
    int t0 = blockIdx.x * 128;
    int n0 = blockIdx.y * 128;
    int b  = blockIdx.z;

    const float* xb = x    + ((size_t)b*Tq + t0) * Dq;
    const float* eb = g_cb + ((size_t)b*Nq + n0) * Dq;

    int fr[2], fj[2];
#pragma unroll
    for (int p = 0; p < 2; p++) {
        int f = tid + p*256;
        fr[p] = f >> 2; fj[p] = (f & 3) * 4;
    }

    float4 xpre[2], epre[2];
#pragma unroll
    for (int p = 0; p < 2; p++) {
        xpre[p] = *(const float4*)(xb + (size_t)fr[p]*Dq + fj[p]);
        epre[p] = *(const float4*)(eb + (size_t)fr[p]*Dq + fj[p]);
    }

    unsigned long long acc[8][4];
#pragma unroll
    for (int i = 0; i < 8; i++)
#pragma unroll
        for (int j = 0; j < 4; j++) acc[i][j] = 0ull;

    for (int c = 0; c < 16; c++) {
        int buf = c & 1;
        float* X = Xs[buf];
        float* E = Es[buf];
        // store prefetched chunk c
#pragma unroll
        for (int p = 0; p < 2; p++) {
            int r = fr[p], kb = fj[p];
            float4 v = xpre[p];
            X[(kb+0)*256 + r*2] = v.x; X[(kb+0)*256 + r*2+1] = v.x;
            X[(kb+1)*256 + r*2] = v.y; X[(kb+1)*256 + r*2+1] = v.y;
            X[(kb+2)*256 + r*2] = v.z; X[(kb+2)*256 + r*2+1] = v.z;
            X[(kb+3)*256 + r*2] = v.w; X[(kb+3)*256 + r*2+1] = v.w;
            float4 w = epre[p];
            E[(kb+0)*128 + r] = w.x;
            E[(kb+1)*128 + r] = w.y;
            E[(kb+2)*128 + r] = w.z;
            E[(kb+3)*128 + r] = w.w;
        }
        __syncthreads();
        // prefetch chunk c+1 (latency hidden under compute below)
        if (c < 15) {
            int kc = (c + 1) * KC;
#pragma unroll
            for (int p = 0; p < 2; p++) {
                xpre[p] = *(const float4*)(xb + (size_t)fr[p]*Dq + kc + fj[p]);
                epre[p] = *(const float4*)(eb + (size_t)fr[p]*Dq + kc + fj[p]);
            }
        }
        // compute chunk c
#pragma unroll
        for (int k = 0; k < KC; k++) {
            const unsigned long long* xp = (const unsigned long long*)(X + k*256 + ty*16);
            const unsigned long long* ep = (const unsigned long long*)(E + k*128 + tx*8);
            unsigned long long xv[8], ev[4];
#pragma unroll
            for (int i = 0; i < 8; i++) xv[i] = xp[i];
#pragma unroll
            for (int j = 0; j < 4; j++) ev[j] = ep[j];
#pragma unroll
            for (int i = 0; i < 8; i++)
#pragma unroll
                for (int j = 0; j < 4; j++)
                    acc[i][j] = fma2(acc[i][j], xv[i], ev[j]);
        }
    }

    // epilogue: dist = (sxx - 2*dot) + see, exactly as reference
    float see8[8];
#pragma unroll
    for (int j = 0; j < 8; j++) see8[j] = g_see[b*Nq + n0 + tx*8 + j];

    int trow = t0 + ty*8;
#pragma unroll
    for (int i = 0; i < 8; i++) {
        float sxx = g_sxx[b*Tq + trow + i];
        unsigned long long best = 0ull;
#pragma unroll
        for (int j2 = 0; j2 < 4; j2++) {
            unsigned long long a = acc[i][j2];
            float dlo = __uint_as_float((unsigned)a);
            float dhi = __uint_as_float((unsigned)(a >> 32));
            float distlo = __fadd_rn(__fsub_rn(sxx, __fmul_rn(2.0f, dlo)), see8[j2*2]);
            float disthi = __fadd_rn(__fsub_rn(sxx, __fmul_rn(2.0f, dhi)), see8[j2*2+1]);
            int nlo = n0 + tx*8 + j2*2;
            unsigned long long klo = make_key(-distlo, nlo);
            unsigned long long khi = make_key(-disthi, nlo + 1);
            if (klo > best) best = klo;
            if (khi > best) best = khi;
        }
#pragma unroll
        for (int off = 8; off > 0; off >>= 1) {
            unsigned long long o = __shfl_down_sync(0xffffffffu, best, off, 16);
            if (o > best) best = o;
        }
        if (tx == 0) atomicMax(&g_best[b*Tq + trow + i], best);
    }
}

// ---------------- kernel 3: gather + outputs + diff partials ----------------
__global__ __launch_bounds__(256) void k_gather(const float* __restrict__ x,
                                                float* __restrict__ out) {
    __shared__ double s_red[8];
    int tid = threadIdx.x, lane = tid & 31, wid = tid >> 5;
    int token = blockIdx.x * 8 + wid;
    int b = token >> 11;

    unsigned long long key = g_best[token];
    unsigned n = 0xFFFFFFFFu - (unsigned)key;

    const float4* q4 = (const float4*)(g_cb + ((size_t)(b*Nq) + n) * Dq);
    const float4* x4 = (const float4*)(x + (size_t)token * Dq);
    float4* o4 = (float4*)(out + (size_t)token * Dq);

    double s = 0.0;
#pragma unroll
    for (int p = 0; p < 2; p++) {
        int f = lane + p*32;
        float4 q = q4[f], xv = x4[f];
        float4 r;
        // exactly: (q + (x + (q - x))) * 0.5  (matches ref fp32 op order)
        float dx = __fsub_rn(q.x, xv.x), dy = __fsub_rn(q.y, xv.y);
        float dz = __fsub_rn(q.z, xv.z), dw = __fsub_rn(q.w, xv.w);
        r.x = __fmul_rn(__fadd_rn(q.x, __fadd_rn(xv.x, dx)), 0.5f);
        r.y = __fmul_rn(__fadd_rn(q.y, __fadd_rn(xv.y, dy)), 0.5f);
        r.z = __fmul_rn(__fadd_rn(q.z, __fadd_rn(xv.z, dz)), 0.5f);
        r.w = __fmul_rn(__fadd_rn(q.w, __fadd_rn(xv.w, dw)), 0.5f);
        o4[f] = r;
        s += (double)dx*(double)dx + (double)dy*(double)dy
           + (double)dz*(double)dz + (double)dw*(double)dw;
    }
    if (lane == 0) out[IND_OFF + token] = (float)n;

#pragma unroll
    for (int off = 16; off > 0; off >>= 1) s += __shfl_down_sync(0xffffffffu, s, off);
    if (lane == 0) s_red[wid] = s;
    __syncthreads();
    if (tid == 0) {
        double t = 0.0;
        for (int i = 0; i < 8; i++) t += s_red[i];
        g_diff_partial[blockIdx.x] = t;
    }
}

// ---------------- kernel 4: deterministic final diff reduce ----------------
__global__ __launch_bounds__(256) void k_diff(float* __restrict__ out) {
    __shared__ double sr[256];
    int tid = threadIdx.x;
    double s = 0.0;
    for (int i = tid; i < 4096; i += 256) s += g_diff_partial[i];
    sr[tid] = s;
    __syncthreads();
    for (int off = 128; off > 0; off >>= 1) {
        if (tid < off) sr[tid] += sr[tid + off];
        __syncthreads();
    }
    if (tid == 0) out[DIFF_OFF] = (float)(sr[0] / (double)Q_ELEMS);
}

// ---------------- launch ----------------
extern "C" void kernel_launch(void* const* d_in, const int* in_sizes, int n_in,
                              void* d_out, int out_size) {
    const float* inp = (const float*)d_in[0];   // (16,2048,256)
    const float* spk = (const float*)d_in[1];   // (3,16,256)
    const float* emb = (const float*)d_in[2];   // (512,256,256)
    float* out = (float*)d_out;                 // [quantize | diff | embed_ind]

    k_prep<<<Bq*Tq/8, 256>>>(inp);
    k_codebook<<<512, 128>>>(emb, spk);
    dim3 g3(Tq/128, Nq/128, Bq);
    k_scores<<<g3, 256>>>(inp);
    k_gather<<<Bq*Tq/8, 256>>>(inp, out);
    k_diff<<<1, 256>>>(out);
}

// round 5
// speedup vs baseline: 1.3645x; 1.3421x over previous
#include <cuda_runtime.h>

#define Bq 16
#define Tq 2048
#define Dq 256
#define Nq 512

#define Q_ELEMS (Bq*Tq*Dq)          /* 8388608 */
#define DIFF_OFF Q_ELEMS
#define IND_OFF  (Q_ELEMS + 1)
#define GATHER_BLOCKS (Bq*Tq/16)    /* 2048 */

// ---------------- scratch (no allocations allowed) ----------------
__device__ float g_cb[Bq*Nq*Dq];              // e codebook [b][n][d], 8 MB
__device__ float g_see[Bq*Nq];                // sum(e^2), XLA-tree order
__device__ float g_sxx[Bq*Tq];                // sum(x^2), XLA-tree order
__device__ unsigned long long g_best[Bq*Tq];  // packed (score,~n) argmax keys
__device__ double g_diff_partial[GATHER_BLOCKS];

// ---------------- helpers ----------------
__device__ __forceinline__ unsigned long long make_key(float s, int n) {
    unsigned u = __float_as_uint(s);
    u = (u & 0x80000000u) ? ~u : (u | 0x80000000u);   // order-preserving float->uint
    return ((unsigned long long)u << 32) | (unsigned long long)(0xFFFFFFFFu - (unsigned)n);
}

__device__ __forceinline__ unsigned long long fma2(unsigned long long a,
                                                   unsigned long long x,
                                                   unsigned long long e) {
    asm("fma.rn.f32x2 %0, %1, %2, %0;" : "+l"(a) : "l"(x), "l"(e));
    return a;
}

__device__ __forceinline__ unsigned long long dup2(float v) {
    unsigned long long r;
    asm("mov.b64 %0, {%1, %1};" : "=l"(r) : "f"(v));
    return r;
}

// XLA warp-tree: shfl_down with descending offsets, acc = rn(acc + other)
__device__ __forceinline__ float warp_tree_sum(float p) {
#pragma unroll
    for (int off = 16; off > 0; off >>= 1)
        p = __fadd_rn(p, __shfl_down_sync(0xffffffffu, p, off));
    return p;
}

// ---------------- kernel 0: sxx[t] (XLA order) + g_best reset ----------------
__global__ __launch_bounds__(256) void k_prep(const float* __restrict__ x) {
    int tid = threadIdx.x, lane = tid & 31, wid = tid >> 5;
    int token = blockIdx.x * 8 + wid;
    const float* xt = x + (size_t)token * Dq;
    float p = 0.f;
#pragma unroll
    for (int j = 0; j < 8; j++) {
        float c = xt[lane + 32*j];
        p = __fadd_rn(p, __fmul_rn(c, c));
    }
    p = warp_tree_sum(p);
    if (lane == 0) {
        g_sxx[token] = p;
        g_best[token] = 0ull;
    }
}

// ---------------- kernel 1: codebook build (unchanged numerics) ----------
__global__ __launch_bounds__(128) void k_codebook(const float* __restrict__ emb,
                                                  const float* __restrict__ spk) {
    __shared__ float As[256*33];   // k-chunk staging; reused as [16][258] in epilogue
    __shared__ float Ms[16*32];
    __shared__ float normS[16];

    int tid = threadIdx.x;
    int lane = tid & 31, wid = tid >> 5;
    int n = blockIdx.x;
    const float* embn = emb + (size_t)n * (Dq*Dq);
    const float* mul  = spk + 2*Bq*Dq;   // spk[2] : [b][k]
    const float* addv = spk + 1*Bq*Dq;   // spk[1] : [b][d]

    float acc[2][16];
#pragma unroll
    for (int r = 0; r < 2; r++)
#pragma unroll
        for (int b = 0; b < 16; b++) acc[r][b] = 0.f;

    for (int kc = 0; kc < 256; kc += 32) {
        __syncthreads();
        for (int i = tid; i < 16*32; i += 128) {
            int b = i >> 5, j = i & 31;
            Ms[i] = mul[b*256 + kc + j];
        }
        for (int f = tid; f < 2048; f += 128) {
            int d = f >> 3, jg = f & 7;
            float4 v = *(const float4*)(embn + (size_t)d*256 + kc + jg*4);
            int base = d*33 + jg*4;
            As[base+0] = v.x; As[base+1] = v.y; As[base+2] = v.z; As[base+3] = v.w;
        }
        __syncthreads();

        const float* a0 = As + tid*33;
        const float* a1 = As + (tid+128)*33;
#pragma unroll 4
        for (int j = 0; j < 32; j++) {
            float x0 = a0[j], x1 = a1[j];
#pragma unroll
            for (int b = 0; b < 16; b++) {
                float m = Ms[b*32 + j];
                acc[0][b] = __fmaf_rn(x0, m, acc[0][b]);
                acc[1][b] = __fmaf_rn(x1, m, acc[1][b]);
            }
        }
    }

    __syncthreads();
#pragma unroll
    for (int r = 0; r < 2; r++)
#pragma unroll
        for (int b = 0; b < 16; b++) As[b*258 + tid + r*128] = acc[r][b];
    __syncthreads();

#pragma unroll
    for (int bb = 0; bb < 4; bb++) {
        int b = wid*4 + bb;
        const float* row = As + b*258;
        float p = 0.f;
#pragma unroll
        for (int j = 0; j < 8; j++) {
            float c = row[lane + 32*j];
            p = __fadd_rn(p, __fmul_rn(c, c));
        }
        p = warp_tree_sum(p);
        if (lane == 0) normS[b] = __fsqrt_rn(p);
    }
    __syncthreads();

#pragma unroll
    for (int r = 0; r < 2; r++) {
        int d = tid + r*128;
#pragma unroll
        for (int b = 0; b < 16; b++) {
            float ef = __fadd_rn(__fdiv_rn(acc[r][b], normS[b]), addv[b*256 + d]);
            g_cb[((size_t)(b*Nq + n))*Dq + d] = ef;
            As[b*258 + d] = ef;
        }
    }
    __syncthreads();

#pragma unroll
    for (int bb = 0; bb < 4; bb++) {
        int b = wid*4 + bb;
        const float* row = As + b*258;
        float p = 0.f;
#pragma unroll
        for (int j = 0; j < 8; j++) {
            float c = row[lane + 32*j];
            p = __fadd_rn(p, __fmul_rn(c, c));
        }
        p = warp_tree_sum(p);
        if (lane == 0) g_see[b*Nq + n] = p;
    }
}

// ---------------- kernel 2: fused score GEMM + argmax ----------------
// No X duplication: x loaded plain, (x,x) built in regs. 1.0 B/MAC smem traffic.
#define KC 16
#define LDW 132
__global__ __launch_bounds__(256, 2) void k_scores(const float* __restrict__ x) {
    __shared__ float Xs[2][KC*LDW];   // [k][128 t], pad 132
    __shared__ float Es[2][KC*LDW];   // [k][128 n], pad 132

    int tid = threadIdx.x;
    int tx = tid & 15, ty = tid >> 4;
    int t0 = blockIdx.x * 128;
    int n0 = blockIdx.y * 128;
    int b  = blockIdx.z;

    const float* xb = x    + ((size_t)b*Tq + t0) * Dq;
    const float* eb = g_cb + ((size_t)b*Nq + n0) * Dq;

    int fr[2], fj[2];
#pragma unroll
    for (int p = 0; p < 2; p++) {
        int f = tid + p*256;
        fr[p] = f >> 2; fj[p] = (f & 3) * 4;
    }

    float4 xpre[2], epre[2];
#pragma unroll
    for (int p = 0; p < 2; p++) {
        xpre[p] = *(const float4*)(xb + (size_t)fr[p]*Dq + fj[p]);
        epre[p] = *(const float4*)(eb + (size_t)fr[p]*Dq + fj[p]);
    }

    unsigned long long acc[8][4];
#pragma unroll
    for (int i = 0; i < 8; i++)
#pragma unroll
        for (int j = 0; j < 4; j++) acc[i][j] = 0ull;

    for (int c = 0; c < 16; c++) {
        int buf = c & 1;
        float* X = Xs[buf];
        float* E = Es[buf];
#pragma unroll
        for (int p = 0; p < 2; p++) {
            int r = fr[p], kb = fj[p];
            float4 v = xpre[p];
            X[(kb+0)*LDW + r] = v.x;
            X[(kb+1)*LDW + r] = v.y;
            X[(kb+2)*LDW + r] = v.z;
            X[(kb+3)*LDW + r] = v.w;
            float4 w = epre[p];
            E[(kb+0)*LDW + r] = w.x;
            E[(kb+1)*LDW + r] = w.y;
            E[(kb+2)*LDW + r] = w.z;
            E[(kb+3)*LDW + r] = w.w;
        }
        __syncthreads();
        if (c < 15) {
            int kc = (c + 1) * KC;
#pragma unroll
            for (int p = 0; p < 2; p++) {
                xpre[p] = *(const float4*)(xb + (size_t)fr[p]*Dq + kc + fj[p]);
                epre[p] = *(const float4*)(eb + (size_t)fr[p]*Dq + kc + fj[p]);
            }
        }
#pragma unroll
        for (int k = 0; k < KC; k++) {
            const float* xrow = X + k*LDW + ty*8;
            const float4 xa = *(const float4*)(xrow);
            const float4 xc = *(const float4*)(xrow + 4);
            const ulonglong2* ep = (const ulonglong2*)(E + k*LDW + tx*8);
            ulonglong2 e0 = ep[0], e1 = ep[1];
            unsigned long long ev[4] = {e0.x, e0.y, e1.x, e1.y};
            unsigned long long xv[8];
            xv[0] = dup2(xa.x); xv[1] = dup2(xa.y);
            xv[2] = dup2(xa.z); xv[3] = dup2(xa.w);
            xv[4] = dup2(xc.x); xv[5] = dup2(xc.y);
            xv[6] = dup2(xc.z); xv[7] = dup2(xc.w);
#pragma unroll
            for (int i = 0; i < 8; i++)
#pragma unroll
                for (int j = 0; j < 4; j++)
                    acc[i][j] = fma2(acc[i][j], xv[i], ev[j]);
        }
    }

    // epilogue: dist = (sxx - 2*dot) + see, exactly as reference
    float see8[8];
#pragma unroll
    for (int j = 0; j < 8; j++) see8[j] = g_see[b*Nq + n0 + tx*8 + j];

    int trow = t0 + ty*8;
#pragma unroll
    for (int i = 0; i < 8; i++) {
        float sxx = g_sxx[b*Tq + trow + i];
        unsigned long long best = 0ull;
#pragma unroll
        for (int j2 = 0; j2 < 4; j2++) {
            unsigned long long a = acc[i][j2];
            float dlo = __uint_as_float((unsigned)a);
            float dhi = __uint_as_float((unsigned)(a >> 32));
            float distlo = __fadd_rn(__fsub_rn(sxx, __fmul_rn(2.0f, dlo)), see8[j2*2]);
            float disthi = __fadd_rn(__fsub_rn(sxx, __fmul_rn(2.0f, dhi)), see8[j2*2+1]);
            int nlo = n0 + tx*8 + j2*2;
            unsigned long long klo = make_key(-distlo, nlo);
            unsigned long long khi = make_key(-disthi, nlo + 1);
            if (klo > best) best = klo;
            if (khi > best) best = khi;
        }
#pragma unroll
        for (int off = 8; off > 0; off >>= 1) {
            unsigned long long o = __shfl_down_sync(0xffffffffu, best, off, 16);
            if (o > best) best = o;
        }
        if (tx == 0) atomicMax(&g_best[b*Tq + trow + i], best);
    }
}

// ---------------- kernel 3: gather + outputs + diff partials (MLP-heavy) ----
__global__ __launch_bounds__(256) void k_gather(const float* __restrict__ x,
                                                float* __restrict__ out) {
    __shared__ unsigned ns[16];
    __shared__ double s_red[8];
    int tid = threadIdx.x, lane = tid & 31, wid = tid >> 5;
    int tok0 = blockIdx.x * 16;
    int b = tok0 >> 11;

    if (tid < 16) {
        unsigned long long key = g_best[tok0 + tid];
        unsigned n = 0xFFFFFFFFu - (unsigned)key;
        ns[tid] = n;
        out[IND_OFF + tok0 + tid] = (float)n;
    }
    __syncthreads();

    const float* cbb = g_cb + (size_t)b * Nq * Dq;
    const float4* x4 = (const float4*)(x + (size_t)tok0 * Dq);
    float4* o4 = (float4*)(out + (size_t)tok0 * Dq);

    float s32 = 0.f;
    double s = 0.0;
#pragma unroll
    for (int i = 0; i < 4; i++) {
        int f = tid + i*256;               // 0..1023 float4 slots
        int tl = f >> 6;                   // local token 0..15
        int dd = (f & 63);                 // float4 index within row
        float4 q = ((const float4*)(cbb + (size_t)ns[tl]*Dq))[dd];
        float4 xv = x4[f];
        float dx = __fsub_rn(q.x, xv.x), dy = __fsub_rn(q.y, xv.y);
        float dz = __fsub_rn(q.z, xv.z), dw = __fsub_rn(q.w, xv.w);
        float4 r;
        r.x = __fmul_rn(__fadd_rn(q.x, __fadd_rn(xv.x, dx)), 0.5f);
        r.y = __fmul_rn(__fadd_rn(q.y, __fadd_rn(xv.y, dy)), 0.5f);
        r.z = __fmul_rn(__fadd_rn(q.z, __fadd_rn(xv.z, dz)), 0.5f);
        r.w = __fmul_rn(__fadd_rn(q.w, __fadd_rn(xv.w, dw)), 0.5f);
        o4[f] = r;
        s32 = fmaf(dx, dx, s32); s32 = fmaf(dy, dy, s32);
        s32 = fmaf(dz, dz, s32); s32 = fmaf(dw, dw, s32);
        if (i == 1) { s += (double)s32; s32 = 0.f; }   // limit fp32 chain length
    }
    s += (double)s32;

#pragma unroll
    for (int off = 16; off > 0; off >>= 1) s += __shfl_down_sync(0xffffffffu, s, off);
    if (lane == 0) s_red[wid] = s;
    __syncthreads();
    if (tid == 0) {
        double t = 0.0;
        for (int i = 0; i < 8; i++) t += s_red[i];
        g_diff_partial[blockIdx.x] = t;
    }
}

// ---------------- kernel 4: deterministic final diff reduce ----------------
__global__ __launch_bounds__(256) void k_diff(float* __restrict__ out) {
    __shared__ double sr[256];
    int tid = threadIdx.x;
    double s = 0.0;
    for (int i = tid; i < GATHER_BLOCKS; i += 256) s += g_diff_partial[i];
    sr[tid] = s;
    __syncthreads();
    for (int off = 128; off > 0; off >>= 1) {
        if (tid < off) sr[tid] += sr[tid + off];
        __syncthreads();
    }
    if (tid == 0) out[DIFF_OFF] = (float)(sr[0] / (double)Q_ELEMS);
}

// ---------------- launch ----------------
extern "C" void kernel_launch(void* const* d_in, const int* in_sizes, int n_in,
                              void* d_out, int out_size) {
    const float* inp = (const float*)d_in[0];   // (16,2048,256)
    const float* spk = (const float*)d_in[1];   // (3,16,256)
    const float* emb = (const float*)d_in[2];   // (512,256,256)
    float* out = (float*)d_out;                 // [quantize | diff | embed_ind]

    k_prep<<<Bq*Tq/8, 256>>>(inp);
    k_codebook<<<512, 128>>>(emb, spk);
    dim3 g3(Tq/128, Nq/128, Bq);
    k_scores<<<g3, 256>>>(inp);
    k_gather<<<GATHER_BLOCKS, 256>>>(inp, out);
    k_diff<<<1, 256>>>(out);
}

// round 6
// speedup vs baseline: 1.4084x; 1.0321x over previous
#include <cuda_runtime.h>

#define Bq 16
#define Tq 2048
#define Dq 256
#define Nq 512

#define Q_ELEMS (Bq*Tq*Dq)          /* 8388608 */
#define DIFF_OFF Q_ELEMS
#define IND_OFF  (Q_ELEMS + 1)
#define GATHER_BLOCKS (Bq*Tq/16)    /* 2048 */
#define NTILES 1024
#define PGRID 296

// ---------------- scratch (no allocations allowed) ----------------
__device__ float g_cb[Bq*Nq*Dq];              // e codebook [b][n][d], 8 MB
__device__ float g_see[Bq*Nq];                // sum(e^2), XLA-tree order
__device__ float g_sxx[Bq*Tq];                // sum(x^2), XLA-tree order
__device__ unsigned long long g_best[Bq*Tq];  // packed (score,~n) argmax keys
__device__ double g_diff_partial[GATHER_BLOCKS];

// ---------------- helpers ----------------
__device__ __forceinline__ unsigned long long make_key(float s, int n) {
    unsigned u = __float_as_uint(s);
    u = (u & 0x80000000u) ? ~u : (u | 0x80000000u);   // order-preserving float->uint
    return ((unsigned long long)u << 32) | (unsigned long long)(0xFFFFFFFFu - (unsigned)n);
}

__device__ __forceinline__ unsigned long long fma2(unsigned long long a,
                                                   unsigned long long x,
                                                   unsigned long long e) {
    asm("fma.rn.f32x2 %0, %1, %2, %0;" : "+l"(a) : "l"(x), "l"(e));
    return a;
}

__device__ __forceinline__ unsigned long long dup2(float v) {
    unsigned long long r;
    asm("mov.b64 %0, {%1, %1};" : "=l"(r) : "f"(v));
    return r;
}

__device__ __forceinline__ unsigned long long pack2(float lo, float hi) {
    unsigned long long r;
    asm("mov.b64 %0, {%1, %2};" : "=l"(r) : "f"(lo), "f"(hi));
    return r;
}

__device__ __forceinline__ void unpack2(unsigned long long v, float& lo, float& hi) {
    asm("mov.b64 {%0, %1}, %2;" : "=f"(lo), "=f"(hi) : "l"(v));
}

// XLA warp-tree: shfl_down with descending offsets, acc = rn(acc + other)
__device__ __forceinline__ float warp_tree_sum(float p) {
#pragma unroll
    for (int off = 16; off > 0; off >>= 1)
        p = __fadd_rn(p, __shfl_down_sync(0xffffffffu, p, off));
    return p;
}

// ---------------- kernel 0: sxx[t] (XLA order) + g_best reset ----------------
__global__ __launch_bounds__(256) void k_prep(const float* __restrict__ x) {
    int tid = threadIdx.x, lane = tid & 31, wid = tid >> 5;
    int token = blockIdx.x * 8 + wid;
    const float* xt = x + (size_t)token * Dq;
    float p = 0.f;
#pragma unroll
    for (int j = 0; j < 8; j++) {
        float c = xt[lane + 32*j];
        p = __fadd_rn(p, __fmul_rn(c, c));
    }
    p = warp_tree_sum(p);
    if (lane == 0) {
        g_sxx[token] = p;
        g_best[token] = 0ull;
    }
}

// ---------------- kernel 1: codebook build (packed f32x2, same chains) ----
__global__ __launch_bounds__(128) void k_codebook(const float* __restrict__ emb,
                                                  const float* __restrict__ spk) {
    __shared__ float As[256*33];               // staging; reused as [16][258] later
    __shared__ unsigned long long Ms2[8*32];   // packed (m[2p],m[2p+1]) per j
    __shared__ float normS[16];

    int tid = threadIdx.x;
    int lane = tid & 31, wid = tid >> 5;
    int n = blockIdx.x;
    const float* embn = emb + (size_t)n * (Dq*Dq);
    const float* mul  = spk + 2*Bq*Dq;   // spk[2] : [b][k]
    const float* addv = spk + 1*Bq*Dq;   // spk[1] : [b][d]

    unsigned long long accp[2][8];       // [d-slot][b-pair], lo=b even, hi=b odd
#pragma unroll
    for (int r = 0; r < 2; r++)
#pragma unroll
        for (int p = 0; p < 8; p++) accp[r][p] = 0ull;

    for (int kc = 0; kc < 256; kc += 32) {
        __syncthreads();
        for (int i = tid; i < 256; i += 128) {
            int p = i >> 5, j = i & 31;
            Ms2[i] = pack2(mul[(2*p)*256 + kc + j], mul[(2*p+1)*256 + kc + j]);
        }
        for (int f = tid; f < 2048; f += 128) {
            int d = f >> 3, jg = f & 7;
            float4 v = *(const float4*)(embn + (size_t)d*256 + kc + jg*4);
            int base = d*33 + jg*4;
            As[base+0] = v.x; As[base+1] = v.y; As[base+2] = v.z; As[base+3] = v.w;
        }
        __syncthreads();

        const float* a0 = As + tid*33;
        const float* a1 = As + (tid+128)*33;
#pragma unroll 4
        for (int j = 0; j < 32; j++) {
            unsigned long long xv0 = dup2(a0[j]);
            unsigned long long xv1 = dup2(a1[j]);
#pragma unroll
            for (int p = 0; p < 8; p++) {
                unsigned long long m = Ms2[p*32 + j];
                accp[0][p] = fma2(accp[0][p], xv0, m);
                accp[1][p] = fma2(accp[1][p], xv1, m);
            }
        }
    }

    // unpack to acc[2][16] (identical chains to scalar version)
    float acc[2][16];
#pragma unroll
    for (int r = 0; r < 2; r++)
#pragma unroll
        for (int p = 0; p < 8; p++)
            unpack2(accp[r][p], acc[r][2*p], acc[r][2*p+1]);

    __syncthreads();
#pragma unroll
    for (int r = 0; r < 2; r++)
#pragma unroll
        for (int b = 0; b < 16; b++) As[b*258 + tid + r*128] = acc[r][b];
    __syncthreads();

#pragma unroll
    for (int bb = 0; bb < 4; bb++) {
        int b = wid*4 + bb;
        const float* row = As + b*258;
        float p = 0.f;
#pragma unroll
        for (int j = 0; j < 8; j++) {
            float c = row[lane + 32*j];
            p = __fadd_rn(p, __fmul_rn(c, c));
        }
        p = warp_tree_sum(p);
        if (lane == 0) normS[b] = __fsqrt_rn(p);
    }
    __syncthreads();

#pragma unroll
    for (int r = 0; r < 2; r++) {
        int d = tid + r*128;
#pragma unroll
        for (int b = 0; b < 16; b++) {
            float ef = __fadd_rn(__fdiv_rn(acc[r][b], normS[b]), addv[b*256 + d]);
            g_cb[((size_t)(b*Nq + n))*Dq + d] = ef;
            As[b*258 + d] = ef;
        }
    }
    __syncthreads();

#pragma unroll
    for (int bb = 0; bb < 4; bb++) {
        int b = wid*4 + bb;
        const float* row = As + b*258;
        float p = 0.f;
#pragma unroll
        for (int j = 0; j < 8; j++) {
            float c = row[lane + 32*j];
            p = __fadd_rn(p, __fmul_rn(c, c));
        }
        p = warp_tree_sum(p);
        if (lane == 0) g_see[b*Nq + n] = p;
    }
}

// ---------------- kernel 2: persistent fused score GEMM + argmax ----------
#define KC 16
#define LDW 132
__global__ __launch_bounds__(256, 2) void k_scores(const float* __restrict__ x) {
    __shared__ float Xs[2][KC*LDW];   // [k][128 t], pad 132
    __shared__ float Es[2][KC*LDW];   // [k][128 n], pad 132

    int tid = threadIdx.x;
    int tx = tid & 15, ty = tid >> 4;

    int fr[2], fj[2];
#pragma unroll
    for (int p = 0; p < 2; p++) {
        int f = tid + p*256;
        fr[p] = f >> 2; fj[p] = (f & 3) * 4;
    }

    for (int tile = blockIdx.x; tile < NTILES; tile += PGRID) {
        int b  = tile >> 6;
        int rem = tile & 63;
        int t0 = (rem >> 2) * 128;
        int n0 = (rem & 3) * 128;

        const float* xb = x    + ((size_t)b*Tq + t0) * Dq;
        const float* eb = g_cb + ((size_t)b*Nq + n0) * Dq;

        float4 xpre[2], epre[2];
#pragma unroll
        for (int p = 0; p < 2; p++) {
            xpre[p] = *(const float4*)(xb + (size_t)fr[p]*Dq + fj[p]);
            epre[p] = *(const float4*)(eb + (size_t)fr[p]*Dq + fj[p]);
        }

        unsigned long long acc[8][4];
#pragma unroll
        for (int i = 0; i < 8; i++)
#pragma unroll
            for (int j = 0; j < 4; j++) acc[i][j] = 0ull;

        for (int c = 0; c < 16; c++) {
            int buf = c & 1;
            float* X = Xs[buf];
            float* E = Es[buf];
#pragma unroll
            for (int p = 0; p < 2; p++) {
                int r = fr[p], kb = fj[p];
                float4 v = xpre[p];
                X[(kb+0)*LDW + r] = v.x;
                X[(kb+1)*LDW + r] = v.y;
                X[(kb+2)*LDW + r] = v.z;
                X[(kb+3)*LDW + r] = v.w;
                float4 w = epre[p];
                E[(kb+0)*LDW + r] = w.x;
                E[(kb+1)*LDW + r] = w.y;
                E[(kb+2)*LDW + r] = w.z;
                E[(kb+3)*LDW + r] = w.w;
            }
            __syncthreads();
            if (c < 15) {
                int kc = (c + 1) * KC;
#pragma unroll
                for (int p = 0; p < 2; p++) {
                    xpre[p] = *(const float4*)(xb + (size_t)fr[p]*Dq + kc + fj[p]);
                    epre[p] = *(const float4*)(eb + (size_t)fr[p]*Dq + kc + fj[p]);
                }
            }
#pragma unroll
            for (int k = 0; k < KC; k++) {
                const float* xrow = X + k*LDW + ty*8;
                const float4 xa = *(const float4*)(xrow);
                const float4 xc = *(const float4*)(xrow + 4);
                const ulonglong2* ep = (const ulonglong2*)(E + k*LDW + tx*8);
                ulonglong2 e0 = ep[0], e1 = ep[1];
                unsigned long long ev[4] = {e0.x, e0.y, e1.x, e1.y};
                unsigned long long xv[8];
                xv[0] = dup2(xa.x); xv[1] = dup2(xa.y);
                xv[2] = dup2(xa.z); xv[3] = dup2(xa.w);
                xv[4] = dup2(xc.x); xv[5] = dup2(xc.y);
                xv[6] = dup2(xc.z); xv[7] = dup2(xc.w);
#pragma unroll
                for (int i = 0; i < 8; i++)
#pragma unroll
                    for (int j = 0; j < 4; j++)
                        acc[i][j] = fma2(acc[i][j], xv[i], ev[j]);
            }
        }

        // epilogue: dist = (sxx - 2*dot) + see, exactly as reference
        float see8[8];
#pragma unroll
        for (int j = 0; j < 8; j++) see8[j] = g_see[b*Nq + n0 + tx*8 + j];

        int trow = t0 + ty*8;
#pragma unroll
        for (int i = 0; i < 8; i++) {
            float sxx = g_sxx[b*Tq + trow + i];
            unsigned long long best = 0ull;
#pragma unroll
            for (int j2 = 0; j2 < 4; j2++) {
                unsigned long long a = acc[i][j2];
                float dlo = __uint_as_float((unsigned)a);
                float dhi = __uint_as_float((unsigned)(a >> 32));
                float distlo = __fadd_rn(__fsub_rn(sxx, __fmul_rn(2.0f, dlo)), see8[j2*2]);
                float disthi = __fadd_rn(__fsub_rn(sxx, __fmul_rn(2.0f, dhi)), see8[j2*2+1]);
                int nlo = n0 + tx*8 + j2*2;
                unsigned long long klo = make_key(-distlo, nlo);
                unsigned long long khi = make_key(-disthi, nlo + 1);
                if (klo > best) best = klo;
                if (khi > best) best = khi;
            }
#pragma unroll
            for (int off = 8; off > 0; off >>= 1) {
                unsigned long long o = __shfl_down_sync(0xffffffffu, best, off, 16);
                if (o > best) best = o;
            }
            if (tx == 0) atomicMax(&g_best[b*Tq + trow + i], best);
        }
    }
}

// ---------------- kernel 3: gather + outputs + diff partials (MLP-heavy) ----
__global__ __launch_bounds__(256) void k_gather(const float* __restrict__ x,
                                                float* __restrict__ out) {
    __shared__ unsigned ns[16];
    __shared__ double s_red[8];
    int tid = threadIdx.x, lane = tid & 31, wid = tid >> 5;
    int tok0 = blockIdx.x * 16;
    int b = tok0 >> 11;

    if (tid < 16) {
        unsigned long long key = g_best[tok0 + tid];
        unsigned n = 0xFFFFFFFFu - (unsigned)key;
        ns[tid] = n;
        out[IND_OFF + tok0 + tid] = (float)n;
    }
    __syncthreads();

    const float* cbb = g_cb + (size_t)b * Nq * Dq;
    const float4* x4 = (const float4*)(x + (size_t)tok0 * Dq);
    float4* o4 = (float4*)(out + (size_t)tok0 * Dq);

    float s32 = 0.f;
    double s = 0.0;
#pragma unroll
    for (int i = 0; i < 4; i++) {
        int f = tid + i*256;
        int tl = f >> 6;
        int dd = (f & 63);
        float4 q = ((const float4*)(cbb + (size_t)ns[tl]*Dq))[dd];
        float4 xv = x4[f];
        float dx = __fsub_rn(q.x, xv.x), dy = __fsub_rn(q.y, xv.y);
        float dz = __fsub_rn(q.z, xv.z), dw = __fsub_rn(q.w, xv.w);
        float4 r;
        r.x = __fmul_rn(__fadd_rn(q.x, __fadd_rn(xv.x, dx)), 0.5f);
        r.y = __fmul_rn(__fadd_rn(q.y, __fadd_rn(xv.y, dy)), 0.5f);
        r.z = __fmul_rn(__fadd_rn(q.z, __fadd_rn(xv.z, dz)), 0.5f);
        r.w = __fmul_rn(__fadd_rn(q.w, __fadd_rn(xv.w, dw)), 0.5f);
        o4[f] = r;
        s32 = fmaf(dx, dx, s32); s32 = fmaf(dy, dy, s32);
        s32 = fmaf(dz, dz, s32); s32 = fmaf(dw, dw, s32);
        if (i == 1) { s += (double)s32; s32 = 0.f; }
    }
    s += (double)s32;

#pragma unroll
    for (int off = 16; off > 0; off >>= 1) s += __shfl_down_sync(0xffffffffu, s, off);
    if (lane == 0) s_red[wid] = s;
    __syncthreads();
    if (tid == 0) {
        double t = 0.0;
        for (int i = 0; i < 8; i++) t += s_red[i];
        g_diff_partial[blockIdx.x] = t;
    }
}

// ---------------- kernel 4: deterministic final diff reduce ----------------
__global__ __launch_bounds__(256) void k_diff(float* __restrict__ out) {
    __shared__ double sr[256];
    int tid = threadIdx.x;
    double s = 0.0;
    for (int i = tid; i < GATHER_BLOCKS; i += 256) s += g_diff_partial[i];
    sr[tid] = s;
    __syncthreads();
    for (int off = 128; off > 0; off >>= 1) {
        if (tid < off) sr[tid] += sr[tid + off];
        __syncthreads();
    }
    if (tid == 0) out[DIFF_OFF] = (float)(sr[0] / (double)Q_ELEMS);
}

// ---------------- launch ----------------
extern "C" void kernel_launch(void* const* d_in, const int* in_sizes, int n_in,
                              void* d_out, int out_size) {
    const float* inp = (const float*)d_in[0];   // (16,2048,256)
    const float* spk = (const float*)d_in[1];   // (3,16,256)
    const float* emb = (const float*)d_in[2];   // (512,256,256)
    float* out = (float*)d_out;                 // [quantize | diff | embed_ind]

    k_prep<<<Bq*Tq/8, 256>>>(inp);
    k_codebook<<<512, 128>>>(emb, spk);
    k_scores<<<PGRID, 256>>>(inp);
    k_gather<<<GATHER_BLOCKS, 256>>>(inp, out);
    k_diff<<<1, 256>>>(out);
}